// round 3
// baseline (speedup 1.0000x reference)
#include <cuda_runtime.h>

// MultiKR fused forward on GB300 (sm_103a), fp32 FFMA path.
//
// Inputs (metadata order):
//  0 user_ids   int32[16384]
//  1 item_ids   int32[16384]
//  2 rec_target f32[16384]
//  3 user_tbl   f32[100000,128]
//  4 item_tbl   f32[50000,128]
//  5 entity_tbl f32[50000,128]
//  6 w_vv f32[128]  7 w_ev f32[128]  8 w_ve f32[128]  9 w_ee f32[128]
// 10 bias_v f32[1] 11 bias_e f32[1]
// 12 Wu f32[128,128] 13 bu f32[128]
// 14 W1 f32[256,256] 15 b1 f32[256]
// 16 W2 f32[256,128] 17 b2 f32[128]
// 18 W3 f32[128,1]   19 b3 f32[1]
// output: concat(rec_out[16384], rec_target[16384]) f32 (handles out_size==B too)

#define B_TOT    16384
#define D        128
#define H1       256
#define H2       128
#define TM       128      // rows per CTA
#define NTHREADS 256
#define KT       16       // k-tile

// dynamic smem layout (float offsets)
//  Us   [    0, 16384)   user acts / later h2
//  Is   [16384, 32768)   item acts
//  Hs   [32768, 49152)   head acts / later h1 half
//  Ws   [49152, 51200)   16x128 weight k-tile
//  vw   [51200, 51712)   w_vv|w_ev|w_ve|w_ee
//  dots [51712, 52224)   hv|iv|he|ie per row
#define SM_FLOATS 52224

__global__ __launch_bounds__(NTHREADS, 1)
void multikr_kernel(const int*   __restrict__ user_ids,
                    const int*   __restrict__ item_ids,
                    const float* __restrict__ rec_target,
                    const float* __restrict__ user_tbl,
                    const float* __restrict__ item_tbl,
                    const float* __restrict__ entity_tbl,
                    const float* __restrict__ w_vv,
                    const float* __restrict__ w_ev,
                    const float* __restrict__ w_ve,
                    const float* __restrict__ w_ee,
                    const float* __restrict__ bias_v_p,
                    const float* __restrict__ bias_e_p,
                    const float* __restrict__ Wu,
                    const float* __restrict__ bu,
                    const float* __restrict__ W1,
                    const float* __restrict__ b1,
                    const float* __restrict__ W2,
                    const float* __restrict__ b2,
                    const float* __restrict__ W3,
                    const float* __restrict__ b3,
                    float* __restrict__ out,
                    int out_size)
{
    extern __shared__ float sm[];
    float* Us   = sm;
    float* Is   = sm + 16384;
    float* Hs   = sm + 32768;
    float* Ws   = sm + 49152;
    float* vw   = sm + 51200;
    float* dots = sm + 51712;

    __shared__ int   s_uid[TM];
    __shared__ int   s_iid[TM];
    __shared__ float s_bu[D];
    __shared__ float s_b2[H2];
    __shared__ float s_w3[H2];

    const int tid = threadIdx.x;
    const int b0  = blockIdx.x * TM;

    if (tid < TM) {
        s_uid[tid] = user_ids[b0 + tid];
        s_iid[tid] = item_ids[b0 + tid];
    }
    if (tid < D) {
        vw[tid]       = w_vv[tid];
        vw[128 + tid] = w_ev[tid];
        vw[256 + tid] = w_ve[tid];
        vw[384 + tid] = w_ee[tid];
        s_bu[tid] = bu[tid];
        s_b2[tid] = b2[tid];
        s_w3[tid] = W3[tid];
    }
    __syncthreads();

    // ---- gather embedding rows (float4) ----
    {
        const float4* ut = (const float4*)user_tbl;
        const float4* it = (const float4*)item_tbl;
        const float4* et = (const float4*)entity_tbl;
        float4* U4 = (float4*)Us;
        float4* I4 = (float4*)Is;
        float4* H4 = (float4*)Hs;
        #pragma unroll
        for (int t = 0; t < (TM * 32) / NTHREADS; ++t) {
            int idx = tid + t * NTHREADS;
            int row = idx >> 5, q = idx & 31;
            U4[idx] = ut[(long)s_uid[row] * 32 + q];
            I4[idx] = it[(long)s_iid[row] * 32 + q];
            H4[idx] = et[(long)s_iid[row] * 32 + q];
        }
    }
    __syncthreads();

    const int tr = tid >> 4;   // 0..15 : rows tr*8 .. tr*8+7
    const int tc = tid & 15;   // 0..15 : cols tc*8 .. tc*8+7
    const int r0 = tr * 8;
    const int c0 = tc * 8;

    const float bias_v = bias_v_p[0];
    const float bias_e = bias_e_p[0];

    // =========================== layer loop ===========================
    for (int layer = 0; layer < 2; ++layer) {
        // ---- user = relu(user @ Wu + bu) ----
        float acc[8][8];
        #pragma unroll
        for (int r = 0; r < 8; ++r)
            #pragma unroll
            for (int c = 0; c < 8; ++c) acc[r][c] = 0.f;

        for (int k0 = 0; k0 < D; k0 += KT) {
            __syncthreads();
            {   // stage Wu[k0..k0+15][0..127] : contiguous 2048 floats
                const float4* w4 = (const float4*)(Wu + k0 * D);
                float4* ws4 = (float4*)Ws;
                ws4[tid]       = w4[tid];
                ws4[tid + 256] = w4[tid + 256];
            }
            __syncthreads();
            #pragma unroll
            for (int kk = 0; kk < KT; ++kk) {
                const int k = k0 + kk;
                float a[8], bb[8];
                #pragma unroll
                for (int r = 0; r < 8; ++r) a[r] = Us[(r0 + r) * D + k];
                float4 v0 = *(const float4*)(Ws + kk * D + c0);
                float4 v1 = *(const float4*)(Ws + kk * D + c0 + 4);
                bb[0]=v0.x; bb[1]=v0.y; bb[2]=v0.z; bb[3]=v0.w;
                bb[4]=v1.x; bb[5]=v1.y; bb[6]=v1.z; bb[7]=v1.w;
                #pragma unroll
                for (int r = 0; r < 8; ++r)
                    #pragma unroll
                    for (int c = 0; c < 8; ++c)
                        acc[r][c] = fmaf(a[r], bb[c], acc[r][c]);
            }
        }
        __syncthreads();   // all reads of Us complete
        #pragma unroll
        for (int r = 0; r < 8; ++r)
            #pragma unroll
            for (int c = 0; c < 8; ++c)
                Us[(r0 + r) * D + c0 + c] = fmaxf(acc[r][c] + s_bu[c0 + c], 0.f);
        __syncthreads();

        // ---- cross-compress ----
        if (tid < TM) {
            const int row = tid;
            const float* ir = Is + row * D;
            const float* hr = Hs + row * D;
            float hv = 0.f, iv = 0.f, he = 0.f, ie = 0.f;
            #pragma unroll 4
            for (int kk = 0; kk < D; ++kk) {
                int k = (kk + row) & (D - 1);      // skew: conflict-free
                float iva = ir[k], hva = hr[k];
                hv = fmaf(hva, vw[k],       hv);
                iv = fmaf(iva, vw[128 + k], iv);
                he = fmaf(hva, vw[256 + k], he);
                ie = fmaf(iva, vw[384 + k], ie);
            }
            dots[row]       = hv;
            dots[128 + row] = iv;
            dots[256 + row] = he;
            dots[384 + row] = ie;
        }
        __syncthreads();
        #pragma unroll
        for (int t = 0; t < (TM * D) / NTHREADS; ++t) {
            int idx = tid + t * NTHREADS;
            int row = idx >> 7;
            float i0 = Is[idx], h0 = Hs[idx];
            float hv = dots[row],       iv = dots[128 + row];
            float he = dots[256 + row], ie = dots[384 + row];
            Is[idx] = fmaf(i0, hv, fmaf(h0, iv, bias_v));
            Hs[idx] = fmaf(i0, he, fmaf(h0, ie, bias_e));
        }
        __syncthreads();
    }

    // ================= MLP: [U|I] @ W1 -> relu -> @ W2 =================
    float acc2[8][8];
    #pragma unroll
    for (int r = 0; r < 8; ++r)
        #pragma unroll
        for (int c = 0; c < 8; ++c) acc2[r][c] = 0.f;

    for (int h = 0; h < 2; ++h) {
        // h1_half = relu(X @ W1[:, h*128 : h*128+128] + b1_half)
        float acc[8][8];
        #pragma unroll
        for (int r = 0; r < 8; ++r)
            #pragma unroll
            for (int c = 0; c < 8; ++c) acc[r][c] = 0.f;

        for (int k0 = 0; k0 < 2 * D; k0 += KT) {
            __syncthreads();
            {   // stage W1[k0..k0+15][h*128 .. h*128+127]
                float4* ws4 = (float4*)Ws;
                #pragma unroll
                for (int t = 0; t < 2; ++t) {
                    int j = tid + t * 256;
                    int rr = j >> 5, c4 = j & 31;
                    ws4[j] = *(const float4*)(W1 + (k0 + rr) * H1 + h * D + c4 * 4);
                }
            }
            __syncthreads();
            const float* Asrc = (k0 < D) ? Us : Is;
            const int kb = k0 & (D - 1);
            #pragma unroll
            for (int kk = 0; kk < KT; ++kk) {
                const int k = kb + kk;
                float a[8], bb[8];
                #pragma unroll
                for (int r = 0; r < 8; ++r) a[r] = Asrc[(r0 + r) * D + k];
                float4 v0 = *(const float4*)(Ws + kk * D + c0);
                float4 v1 = *(const float4*)(Ws + kk * D + c0 + 4);
                bb[0]=v0.x; bb[1]=v0.y; bb[2]=v0.z; bb[3]=v0.w;
                bb[4]=v1.x; bb[5]=v1.y; bb[6]=v1.z; bb[7]=v1.w;
                #pragma unroll
                for (int r = 0; r < 8; ++r)
                    #pragma unroll
                    for (int c = 0; c < 8; ++c)
                        acc[r][c] = fmaf(a[r], bb[c], acc[r][c]);
            }
        }
        __syncthreads();   // prior Hs readers (GEMM3 of half 0 / layer loop) done
        #pragma unroll
        for (int r = 0; r < 8; ++r)
            #pragma unroll
            for (int c = 0; c < 8; ++c)
                Hs[(r0 + r) * D + c0 + c] =
                    fmaxf(acc[r][c] + b1[h * D + c0 + c], 0.f);
        __syncthreads();

        // acc2 += h1_half @ W2[h*128 .. h*128+127][:]
        for (int k0 = 0; k0 < D; k0 += KT) {
            __syncthreads();
            {   // W2 tile is contiguous 2048 floats
                const float4* w4 = (const float4*)(W2 + (h * D + k0) * H2);
                float4* ws4 = (float4*)Ws;
                ws4[tid]       = w4[tid];
                ws4[tid + 256] = w4[tid + 256];
            }
            __syncthreads();
            #pragma unroll
            for (int kk = 0; kk < KT; ++kk) {
                const int k = k0 + kk;
                float a[8], bb[8];
                #pragma unroll
                for (int r = 0; r < 8; ++r) a[r] = Hs[(r0 + r) * D + k];
                float4 v0 = *(const float4*)(Ws + kk * H2 + c0);
                float4 v1 = *(const float4*)(Ws + kk * H2 + c0 + 4);
                bb[0]=v0.x; bb[1]=v0.y; bb[2]=v0.z; bb[3]=v0.w;
                bb[4]=v1.x; bb[5]=v1.y; bb[6]=v1.z; bb[7]=v1.w;
                #pragma unroll
                for (int r = 0; r < 8; ++r)
                    #pragma unroll
                    for (int c = 0; c < 8; ++c)
                        acc2[r][c] = fmaf(a[r], bb[c], acc2[r][c]);
            }
        }
        __syncthreads();   // Hs reads for this half done -> next half may overwrite
    }

    // h2 = relu(acc2 + b2)  -> store into Us (dead)
    #pragma unroll
    for (int r = 0; r < 8; ++r)
        #pragma unroll
        for (int c = 0; c < 8; ++c)
            Us[(r0 + r) * D + c0 + c] = fmaxf(acc2[r][c] + s_b2[c0 + c], 0.f);
    __syncthreads();

    // out = relu(h2 @ W3 + b3)
    if (tid < TM) {
        const int row = tid;
        const float* hr = Us + row * D;
        float d = 0.f;
        #pragma unroll 4
        for (int kk = 0; kk < D; ++kk) {
            int k = (kk + row) & (D - 1);   // skewed, conflict-free
            d = fmaf(hr[k], s_w3[k], d);
        }
        out[b0 + row] = fmaxf(d + b3[0], 0.f);
        if (out_size >= 2 * B_TOT)
            out[B_TOT + b0 + row] = rec_target[b0 + row];
    }
}

extern "C" void kernel_launch(void* const* d_in, const int* in_sizes, int n_in,
                              void* d_out, int out_size)
{
    (void)n_in; (void)in_sizes;
    const int*   user_ids   = (const int*)  d_in[0];
    const int*   item_ids   = (const int*)  d_in[1];
    const float* rec_target = (const float*)d_in[2];
    const float* user_tbl   = (const float*)d_in[3];
    const float* item_tbl   = (const float*)d_in[4];
    const float* entity_tbl = (const float*)d_in[5];
    const float* w_vv   = (const float*)d_in[6];
    const float* w_ev   = (const float*)d_in[7];
    const float* w_ve   = (const float*)d_in[8];
    const float* w_ee   = (const float*)d_in[9];
    const float* bias_v = (const float*)d_in[10];
    const float* bias_e = (const float*)d_in[11];
    const float* Wu = (const float*)d_in[12];
    const float* bu = (const float*)d_in[13];
    const float* W1 = (const float*)d_in[14];
    const float* b1 = (const float*)d_in[15];
    const float* W2 = (const float*)d_in[16];
    const float* b2 = (const float*)d_in[17];
    const float* W3 = (const float*)d_in[18];
    const float* b3 = (const float*)d_in[19];

    const size_t smem = SM_FLOATS * sizeof(float);   // ~204 KB
    cudaFuncSetAttribute(multikr_kernel,
                         cudaFuncAttributeMaxDynamicSharedMemorySize, (int)smem);

    multikr_kernel<<<B_TOT / TM, NTHREADS, smem>>>(
        user_ids, item_ids, rec_target, user_tbl, item_tbl, entity_tbl,
        w_vv, w_ev, w_ve, w_ee, bias_v, bias_e,
        Wu, bu, W1, b1, W2, b2, W3, b3,
        (float*)d_out, out_size);
}

// round 4
// speedup vs baseline: 1.1338x; 1.1338x over previous
#include <cuda_runtime.h>

// MultiKR fused forward on GB300 (sm_103a), fp32 FFMA path, v2:
//  - 16x4 register microtile (warp-uniform broadcast A loads, coalesced B loads)
//  - cp.async double-buffered weight k-tiles (1 barrier per tile, L2 latency hidden)
//
// Inputs (metadata order):
//  0 user_ids   int32[16384]
//  1 item_ids   int32[16384]
//  2 rec_target f32[16384]
//  3 user_tbl   f32[100000,128]
//  4 item_tbl   f32[50000,128]
//  5 entity_tbl f32[50000,128]
//  6 w_vv f32[128]  7 w_ev f32[128]  8 w_ve f32[128]  9 w_ee f32[128]
// 10 bias_v f32[1] 11 bias_e f32[1]
// 12 Wu f32[128,128] 13 bu f32[128]
// 14 W1 f32[256,256] 15 b1 f32[256]
// 16 W2 f32[256,128] 17 b2 f32[128]
// 18 W3 f32[128,1]   19 b3 f32[1]
// output: concat(rec_out[16384], rec_target[16384]) f32

#define B_TOT    16384
#define D        128
#define H1       256
#define H2       128
#define TM       128      // rows per CTA
#define NTHREADS 256
#define KT       16       // k-tile rows

// dynamic smem (float offsets)
//  Us   [    0, 16384)
//  Is   [16384, 32768)
//  Hs   [32768, 49152)
//  Ws   [49152, 53248)   two 16x128 weight buffers (2048 floats each)
//  vw   [53248, 53760)
//  dots [53760, 54272)
#define SM_FLOATS 54272

__device__ __forceinline__ void cp16(float* dst, const float* src) {
    unsigned s = (unsigned)__cvta_generic_to_shared(dst);
    asm volatile("cp.async.cg.shared.global [%0], [%1], 16;\n" :: "r"(s), "l"(src));
}
#define CP_COMMIT() asm volatile("cp.async.commit_group;\n" ::: "memory")
#define CP_WAIT0()  asm volatile("cp.async.wait_group 0;\n" ::: "memory")

// stage a contiguous 16x128 float tile (2048 floats)
__device__ __forceinline__ void stage_contig(float* dst, const float* src, int tid) {
    cp16(dst + tid * 4,         src + tid * 4);
    cp16(dst + (tid + 256) * 4, src + (tid + 256) * 4);
}
// stage W1[k0..k0+15][h*128 .. h*128+127] (row stride 256)
__device__ __forceinline__ void stage_w1(float* dst, const float* W1, int k0, int h, int tid) {
    #pragma unroll
    for (int t = 0; t < 2; ++t) {
        int j  = tid + t * 256;
        int rr = j >> 5, c4 = j & 31;
        cp16(dst + rr * 128 + c4 * 4, W1 + (k0 + rr) * H1 + h * 128 + c4 * 4);
    }
}

// one 16-k tile of C[16x4] += A[16rows x 16k] * W[16k x 4cols]
__device__ __forceinline__ void mm_tile(const float* __restrict__ A,
                                        const float* __restrict__ W,
                                        float acc[16][4], int r0, int c0, int kbase)
{
    #pragma unroll
    for (int kc = 0; kc < KT; kc += 4) {
        float4 b0 = *(const float4*)(W + (kc + 0) * 128 + c0);
        float4 b1 = *(const float4*)(W + (kc + 1) * 128 + c0);
        float4 b2 = *(const float4*)(W + (kc + 2) * 128 + c0);
        float4 b3 = *(const float4*)(W + (kc + 3) * 128 + c0);
        #pragma unroll
        for (int r = 0; r < 16; ++r) {
            float4 a4 = *(const float4*)(A + (r0 + r) * D + kbase + kc);
            acc[r][0] = fmaf(a4.x, b0.x, acc[r][0]);
            acc[r][1] = fmaf(a4.x, b0.y, acc[r][1]);
            acc[r][2] = fmaf(a4.x, b0.z, acc[r][2]);
            acc[r][3] = fmaf(a4.x, b0.w, acc[r][3]);
            acc[r][0] = fmaf(a4.y, b1.x, acc[r][0]);
            acc[r][1] = fmaf(a4.y, b1.y, acc[r][1]);
            acc[r][2] = fmaf(a4.y, b1.z, acc[r][2]);
            acc[r][3] = fmaf(a4.y, b1.w, acc[r][3]);
            acc[r][0] = fmaf(a4.z, b2.x, acc[r][0]);
            acc[r][1] = fmaf(a4.z, b2.y, acc[r][1]);
            acc[r][2] = fmaf(a4.z, b2.z, acc[r][2]);
            acc[r][3] = fmaf(a4.z, b2.w, acc[r][3]);
            acc[r][0] = fmaf(a4.w, b3.x, acc[r][0]);
            acc[r][1] = fmaf(a4.w, b3.y, acc[r][1]);
            acc[r][2] = fmaf(a4.w, b3.z, acc[r][2]);
            acc[r][3] = fmaf(a4.w, b3.w, acc[r][3]);
        }
    }
}

__global__ __launch_bounds__(NTHREADS, 1)
void multikr_kernel(const int*   __restrict__ user_ids,
                    const int*   __restrict__ item_ids,
                    const float* __restrict__ rec_target,
                    const float* __restrict__ user_tbl,
                    const float* __restrict__ item_tbl,
                    const float* __restrict__ entity_tbl,
                    const float* __restrict__ w_vv,
                    const float* __restrict__ w_ev,
                    const float* __restrict__ w_ve,
                    const float* __restrict__ w_ee,
                    const float* __restrict__ bias_v_p,
                    const float* __restrict__ bias_e_p,
                    const float* __restrict__ Wu,
                    const float* __restrict__ bu,
                    const float* __restrict__ W1,
                    const float* __restrict__ b1,
                    const float* __restrict__ W2,
                    const float* __restrict__ b2,
                    const float* __restrict__ W3,
                    const float* __restrict__ b3,
                    float* __restrict__ out,
                    int out_size)
{
    extern __shared__ float sm[];
    float* Us   = sm;
    float* Is   = sm + 16384;
    float* Hs   = sm + 32768;
    float* Ws   = sm + 49152;          // Ws + 2048 = second buffer
    float* vw   = sm + 53248;
    float* dots = sm + 53760;

    __shared__ int   s_uid[TM];
    __shared__ int   s_iid[TM];
    __shared__ float s_bu[D];
    __shared__ float s_b2[H2];
    __shared__ float s_w3[H2];

    const int tid = threadIdx.x;
    const int b0  = blockIdx.x * TM;

    if (tid < TM) {
        s_uid[tid] = user_ids[b0 + tid];
        s_iid[tid] = item_ids[b0 + tid];
    }
    if (tid < D) {
        vw[tid]       = w_vv[tid];
        vw[128 + tid] = w_ev[tid];
        vw[256 + tid] = w_ve[tid];
        vw[384 + tid] = w_ee[tid];
        s_bu[tid] = bu[tid];
        s_b2[tid] = b2[tid];
        s_w3[tid] = W3[tid];
    }
    __syncthreads();

    // ---- gather embedding rows (coalesced float4) ----
    {
        const float4* ut = (const float4*)user_tbl;
        const float4* it = (const float4*)item_tbl;
        const float4* et = (const float4*)entity_tbl;
        float4* U4 = (float4*)Us;
        float4* I4 = (float4*)Is;
        float4* H4 = (float4*)Hs;
        #pragma unroll
        for (int t = 0; t < (TM * 32) / NTHREADS; ++t) {
            int idx = tid + t * NTHREADS;
            int row = idx >> 5, q = idx & 31;
            U4[idx] = ut[(long)s_uid[row] * 32 + q];
            I4[idx] = it[(long)s_iid[row] * 32 + q];
            H4[idx] = et[(long)s_iid[row] * 32 + q];
        }
    }
    __syncthreads();

    const int r0 = (tid >> 5) * 16;    // warp -> 16 rows
    const int c0 = (tid & 31) * 4;     // lane -> 4 cols

    const float bias_v = bias_v_p[0];
    const float bias_e = bias_e_p[0];

    // =========================== layer loop ===========================
    for (int layer = 0; layer < 2; ++layer) {
        // ---- user = relu(user @ Wu + bu) ----
        float acc[16][4];
        #pragma unroll
        for (int r = 0; r < 16; ++r)
            #pragma unroll
            for (int c = 0; c < 4; ++c) acc[r][c] = 0.f;

        stage_contig(Ws, Wu, tid); CP_COMMIT();
        for (int t = 0; t < 8; ++t) {
            CP_WAIT0(); __syncthreads();
            if (t + 1 < 8) { stage_contig(Ws + ((t + 1) & 1) * 2048, Wu + (t + 1) * KT * D, tid); CP_COMMIT(); }
            mm_tile(Us, Ws + (t & 1) * 2048, acc, r0, c0, t * KT);
        }
        __syncthreads();     // readers of Us done -> in-place store OK
        #pragma unroll
        for (int r = 0; r < 16; ++r) {
            float4 v;
            v.x = fmaxf(acc[r][0] + s_bu[c0 + 0], 0.f);
            v.y = fmaxf(acc[r][1] + s_bu[c0 + 1], 0.f);
            v.z = fmaxf(acc[r][2] + s_bu[c0 + 2], 0.f);
            v.w = fmaxf(acc[r][3] + s_bu[c0 + 3], 0.f);
            *(float4*)(Us + (r0 + r) * D + c0) = v;
        }
        __syncthreads();

        // ---- cross-compress ----
        if (tid < TM) {
            const int row = tid;
            const float* ir = Is + row * D;
            const float* hr = Hs + row * D;
            float hv = 0.f, iv = 0.f, he = 0.f, ie = 0.f;
            #pragma unroll 4
            for (int kk = 0; kk < D; ++kk) {
                int k = (kk + row) & (D - 1);
                float iva = ir[k], hva = hr[k];
                hv = fmaf(hva, vw[k],       hv);
                iv = fmaf(iva, vw[128 + k], iv);
                he = fmaf(hva, vw[256 + k], he);
                ie = fmaf(iva, vw[384 + k], ie);
            }
            dots[row]       = hv;
            dots[128 + row] = iv;
            dots[256 + row] = he;
            dots[384 + row] = ie;
        }
        __syncthreads();
        #pragma unroll
        for (int t = 0; t < (TM * D) / NTHREADS; ++t) {
            int idx = tid + t * NTHREADS;
            int row = idx >> 7;
            float i0 = Is[idx], h0 = Hs[idx];
            float hv = dots[row],       iv = dots[128 + row];
            float he = dots[256 + row], ie = dots[384 + row];
            Is[idx] = fmaf(i0, hv, fmaf(h0, iv, bias_v));
            Hs[idx] = fmaf(i0, he, fmaf(h0, ie, bias_e));
        }
        __syncthreads();
    }

    // ================= MLP: [U|I] @ W1 -> relu -> @ W2 =================
    float acc2[16][4];
    #pragma unroll
    for (int r = 0; r < 16; ++r)
        #pragma unroll
        for (int c = 0; c < 4; ++c) acc2[r][c] = 0.f;

    for (int h = 0; h < 2; ++h) {
        // h1_half = relu(X @ W1[:, h*128 .. h*128+128] + b1_half)  (X = [Us | Is], K=256)
        float acc[16][4];
        #pragma unroll
        for (int r = 0; r < 16; ++r)
            #pragma unroll
            for (int c = 0; c < 4; ++c) acc[r][c] = 0.f;

        stage_w1(Ws, W1, 0, h, tid); CP_COMMIT();
        for (int t = 0; t < 16; ++t) {
            CP_WAIT0(); __syncthreads();
            if (t + 1 < 16) { stage_w1(Ws + ((t + 1) & 1) * 2048, W1, (t + 1) * KT, h, tid); CP_COMMIT(); }
            const float* Asrc = (t < 8) ? Us : Is;
            mm_tile(Asrc, Ws + (t & 1) * 2048, acc, r0, c0, (t * KT) & (D - 1));
        }
        __syncthreads();     // prior Hs readers done
        {
            float4 b1v = *(const float4*)(b1 + h * 128 + c0);
            #pragma unroll
            for (int r = 0; r < 16; ++r) {
                float4 v;
                v.x = fmaxf(acc[r][0] + b1v.x, 0.f);
                v.y = fmaxf(acc[r][1] + b1v.y, 0.f);
                v.z = fmaxf(acc[r][2] + b1v.z, 0.f);
                v.w = fmaxf(acc[r][3] + b1v.w, 0.f);
                *(float4*)(Hs + (r0 + r) * D + c0) = v;
            }
        }
        __syncthreads();

        // acc2 += h1_half @ W2[h*128 .. h*128+127][:]
        stage_contig(Ws, W2 + (h * 128) * H2, tid); CP_COMMIT();
        for (int t = 0; t < 8; ++t) {
            CP_WAIT0(); __syncthreads();
            if (t + 1 < 8) { stage_contig(Ws + ((t + 1) & 1) * 2048, W2 + (h * 128 + (t + 1) * KT) * H2, tid); CP_COMMIT(); }
            mm_tile(Hs, Ws + (t & 1) * 2048, acc2, r0, c0, t * KT);
        }
        __syncthreads();     // Hs reads done -> next half may overwrite
    }

    // h2 = relu(acc2 + b2) -> Us (dead)
    #pragma unroll
    for (int r = 0; r < 16; ++r) {
        float4 v;
        v.x = fmaxf(acc2[r][0] + s_b2[c0 + 0], 0.f);
        v.y = fmaxf(acc2[r][1] + s_b2[c0 + 1], 0.f);
        v.z = fmaxf(acc2[r][2] + s_b2[c0 + 2], 0.f);
        v.w = fmaxf(acc2[r][3] + s_b2[c0 + 3], 0.f);
        *(float4*)(Us + (r0 + r) * D + c0) = v;
    }
    __syncthreads();

    // out = relu(h2 @ W3 + b3)
    if (tid < TM) {
        const int row = tid;
        const float* hr = Us + row * D;
        float d = 0.f;
        #pragma unroll 4
        for (int kk = 0; kk < D; ++kk) {
            int k = (kk + row) & (D - 1);
            d = fmaf(hr[k], s_w3[k], d);
        }
        out[b0 + row] = fmaxf(d + b3[0], 0.f);
        if (out_size >= 2 * B_TOT)
            out[B_TOT + b0 + row] = rec_target[b0 + row];
    }
}

extern "C" void kernel_launch(void* const* d_in, const int* in_sizes, int n_in,
                              void* d_out, int out_size)
{
    (void)n_in; (void)in_sizes;
    const int*   user_ids   = (const int*)  d_in[0];
    const int*   item_ids   = (const int*)  d_in[1];
    const float* rec_target = (const float*)d_in[2];
    const float* user_tbl   = (const float*)d_in[3];
    const float* item_tbl   = (const float*)d_in[4];
    const float* entity_tbl = (const float*)d_in[5];
    const float* w_vv   = (const float*)d_in[6];
    const float* w_ev   = (const float*)d_in[7];
    const float* w_ve   = (const float*)d_in[8];
    const float* w_ee   = (const float*)d_in[9];
    const float* bias_v = (const float*)d_in[10];
    const float* bias_e = (const float*)d_in[11];
    const float* Wu = (const float*)d_in[12];
    const float* bu = (const float*)d_in[13];
    const float* W1 = (const float*)d_in[14];
    const float* b1 = (const float*)d_in[15];
    const float* W2 = (const float*)d_in[16];
    const float* b2 = (const float*)d_in[17];
    const float* W3 = (const float*)d_in[18];
    const float* b3 = (const float*)d_in[19];

    const size_t smem = SM_FLOATS * sizeof(float);   // ~212 KB
    cudaFuncSetAttribute(multikr_kernel,
                         cudaFuncAttributeMaxDynamicSharedMemorySize, (int)smem);

    multikr_kernel<<<B_TOT / TM, NTHREADS, smem>>>(
        user_ids, item_ids, rec_target, user_tbl, item_tbl, entity_tbl,
        w_vv, w_ev, w_ve, w_ee, bias_v, bias_e,
        Wu, bu, W1, b1, W2, b2, W3, b3,
        (float*)d_out, out_size);
}